// round 6
// baseline (speedup 1.0000x reference)
#include <cuda_runtime.h>
#include <math.h>

#define NPT 4096
#define TPB 256
#define JPT 16          // j-elements per thread (NPT / TPB)
#define RPB 4           // rows per block (amortizes register-cached loads)
#define EPSF 0.1f
#define IEPS 10.0f
#define K2E 1.4426950408889634f   // log2(e)
#define LN2F 0.6931471805599453f

__device__ float d_u[NPT];
__device__ float d_v[NPT];
__device__ float d_part[NPT];

__device__ __forceinline__ float fast_ex2(float x) {
    float r;
    asm("ex2.approx.ftz.f32 %0, %1;" : "=f"(r) : "f"(x));
    return r;
}
__device__ __forceinline__ float fast_lg2(float x) {
    float r;
    asm("lg2.approx.ftz.f32 %0, %1;" : "=f"(r) : "f"(x));
    return r;
}

__global__ __launch_bounds__(TPB) void init_uv() {
    int i = blockIdx.x * TPB + threadIdx.x;
    d_u[i] = 0.f;
    d_v[i] = 0.f;
}

// out[row] = cmu - EPS * logsumexp_j( (w[j] - C(row, j)) / EPS )
// DIR==0: rows over X, reduce over Y with w = v, out = u
// DIR==1: rows over Y, reduce over X with w = u, out = v
template <int DIR>
__global__ __launch_bounds__(TPB) void lse_kernel(const float2* __restrict__ X,
                                                  const float2* __restrict__ Y,
                                                  float cmu) {
    const float2* A = (DIR == 0) ? X : Y;
    const float2* B = (DIR == 0) ? Y : X;
    const float*  w = (DIR == 0) ? d_v : d_u;
    float*      out = (DIR == 0) ? d_u : d_v;

    __shared__ float red[TPB / 32];
    __shared__ float bc;

    const int t = threadIdx.x;
    const int j0 = t * JPT;

    // Register-cache this thread's chunk of B points and pre-scaled weights.
    float b0[JPT], b1[JPT], w10[JPT];
    const float4* B4 = (const float4*)B;   // 2 float2 points per float4
    const float4* W4 = (const float4*)w;
#pragma unroll
    for (int k = 0; k < JPT / 2; k++) {
        float4 p = B4[j0 / 2 + k];
        b0[2 * k]     = p.x;  b1[2 * k]     = p.y;
        b0[2 * k + 1] = p.z;  b1[2 * k + 1] = p.w;
    }
#pragma unroll
    for (int k = 0; k < JPT / 4; k++) {
        float4 ww = W4[j0 / 4 + k];
        w10[4 * k]     = ww.x * IEPS;
        w10[4 * k + 1] = ww.y * IEPS;
        w10[4 * k + 2] = ww.z * IEPS;
        w10[4 * k + 3] = ww.w * IEPS;
    }

    for (int r = 0; r < RPB; r++) {
        const int row = blockIdx.x * RPB + r;
        const float2 a = A[row];

        // Pass 1: compute scaled arguments, track local max.
        float tv[JPT];
        float m = -3.4e38f;
#pragma unroll
        for (int k = 0; k < JPT; k++) {
            float dx = a.x - b0[k];
            float dy = a.y - b1[k];
            float c  = fabsf(dx) + fabsf(dy);       // |dx|+|dy| (abs folds into FADD)
            float x  = fmaf(c, -IEPS, w10[k]);      // (w - c) * 10
            tv[k] = x;
            m = fmaxf(m, x);
        }

        // Block max
        __syncthreads();   // protect red[] reuse across rows
#pragma unroll
        for (int o = 16; o; o >>= 1) m = fmaxf(m, __shfl_xor_sync(0xffffffffu, m, o));
        if ((t & 31) == 0) red[t >> 5] = m;
        __syncthreads();
        if (t < 32) {
            float v = (t < TPB / 32) ? red[t] : -3.4e38f;
#pragma unroll
            for (int o = 4; o; o >>= 1) v = fmaxf(v, __shfl_xor_sync(0xffffffffu, v, o));
            if (t == 0) bc = v;
        }
        __syncthreads();
        m = bc;

        // Pass 2: sum of exp(tv - m) via exp2
        const float mk = m * K2E;
        float s = 0.f;
#pragma unroll
        for (int k = 0; k < JPT; k++)
            s += fast_ex2(fmaf(tv[k], K2E, -mk));

        // Block sum
        __syncthreads();
#pragma unroll
        for (int o = 16; o; o >>= 1) s += __shfl_xor_sync(0xffffffffu, s, o);
        if ((t & 31) == 0) red[t >> 5] = s;
        __syncthreads();
        if (t == 0) {
            float tot = 0.f;
#pragma unroll
            for (int i = 0; i < TPB / 32; i++) tot += red[i];
            // out = cmu - EPS * (m + ln(tot))
            out[row] = cmu - EPSF * (m + fast_lg2(tot) * LN2F);
        }
    }
}

// Writes pi and C, accumulates per-row sum(pi*C) into d_part[row].
__global__ __launch_bounds__(TPB) void final_kernel(const float2* __restrict__ X,
                                                    const float2* __restrict__ Y,
                                                    float* __restrict__ pi_out,
                                                    float* __restrict__ c_out) {
    __shared__ float red[TPB / 32];
    const int row = blockIdx.x;
    const int t = threadIdx.x;
    const float2 a = X[row];
    const float u10 = d_u[row] * IEPS;

    float s = 0.f;
    const int j0 = t * JPT;
#pragma unroll
    for (int k = 0; k < JPT; k++) {
        int j = j0 + k;
        float2 b = Y[j];
        float c  = fabsf(a.x - b.x) + fabsf(a.y - b.y);
        float arg = (u10 + d_v[j] * IEPS - c * IEPS) * K2E;
        float pi = fast_ex2(arg);
        size_t idx = (size_t)row * NPT + j;
        if (pi_out) pi_out[idx] = pi;
        if (c_out)  c_out[idx]  = c;
        s += pi * c;
    }
#pragma unroll
    for (int o = 16; o; o >>= 1) s += __shfl_xor_sync(0xffffffffu, s, o);
    if ((t & 31) == 0) red[t >> 5] = s;
    __syncthreads();
    if (t == 0) {
        float tot = 0.f;
#pragma unroll
        for (int i = 0; i < TPB / 32; i++) tot += red[i];
        d_part[row] = tot;
    }
}

// Deterministic final reduction of d_part into out[0] (double accumulation).
__global__ __launch_bounds__(TPB) void reduce_kernel(float* __restrict__ out) {
    __shared__ double red[TPB / 32];
    const int t = threadIdx.x;
    double s = 0.0;
    for (int i = t; i < NPT; i += TPB) s += (double)d_part[i];
#pragma unroll
    for (int o = 16; o; o >>= 1) s += __shfl_xor_sync(0xffffffffu, s, o);
    if ((t & 31) == 0) red[t >> 5] = s;
    __syncthreads();
    if (t == 0) {
        double tot = 0.0;
#pragma unroll
        for (int i = 0; i < TPB / 32; i++) tot += red[i];
        out[0] = (float)tot;
    }
}

extern "C" void kernel_launch(void* const* d_in, const int* in_sizes, int n_in,
                              void* d_out, int out_size) {
    const float2* x = (const float2*)d_in[0];
    const float2* y = (const float2*)d_in[1];
    float* out = (float*)d_out;

    // EPS * log(1/N + 1e-8)  (log_mu == log_nu since n == m)
    const float cmu = (float)(0.1 * log(1.0 / 4096.0 + 1e-8));

    init_uv<<<NPT / TPB, TPB>>>();

    for (int it = 0; it < 50; ++it) {
        lse_kernel<0><<<NPT / RPB, TPB>>>(x, y, cmu);  // update u (uses v)
        lse_kernel<1><<<NPT / RPB, TPB>>>(x, y, cmu);  // update v (uses new u)
    }

    // Output layout: [cost, pi (N*N row-major), C (N*N row-major)]
    float* pi_out = nullptr;
    float* c_out  = nullptr;
    const long long need = 1LL + 2LL * NPT * NPT;
    if ((long long)out_size >= need) {
        pi_out = out + 1;
        c_out  = out + 1 + (size_t)NPT * NPT;
    }
    final_kernel<<<NPT, TPB>>>(x, y, pi_out, c_out);
    reduce_kernel<<<1, TPB>>>(out);
}

// round 7
// speedup vs baseline: 1.8762x; 1.8762x over previous
#include <cuda_runtime.h>
#include <math.h>

#define NPT 4096
#define TPB 256
#define JPT 16          // j-elements per thread (NPT / TPB)
#define RPB 8           // rows per block (one barrier per 8 rows)
#define EPSF 0.1f
#define IEPS 10.0f
#define K2E 1.4426950408889634f        // log2(e)
#define SCL (IEPS * K2E)               // 14.4269504...  (positive -> commutes with abs)
#define ELN2 0.0693147180559945f       // EPS * ln(2)

__device__ float d_u[NPT];
__device__ float d_v[NPT];
__device__ float d_part[NPT];

__device__ __forceinline__ float fast_ex2(float x) {
    float r;
    asm("ex2.approx.ftz.f32 %0, %1;" : "=f"(r) : "f"(x));
    return r;
}
__device__ __forceinline__ float fast_lg2(float x) {
    float r;
    asm("lg2.approx.ftz.f32 %0, %1;" : "=f"(r) : "f"(x));
    return r;
}

__global__ __launch_bounds__(TPB) void init_uv() {
    int i = blockIdx.x * TPB + threadIdx.x;
    d_u[i] = 0.f;
    d_v[i] = 0.f;
}

// out[row] = cmu - EPS * ln( sum_j exp((w[j] - C(row,j)) / EPS) )
// Computed unshifted in log2 domain: all coordinates/weights pre-scaled by
// SCL = 10*log2(e), so per element: 3 FADD + 1 FADD + EX2 + sum-FADD.
// DIR==0: rows over X, reduce over Y with w = v, out = u
// DIR==1: rows over Y, reduce over X with w = u, out = v
template <int DIR>
__global__ __launch_bounds__(TPB, 3) void lse_kernel(const float2* __restrict__ X,
                                                     const float2* __restrict__ Y,
                                                     float cmu) {
    const float2* A = (DIR == 0) ? X : Y;
    const float2* B = (DIR == 0) ? Y : X;
    const float*  w = (DIR == 0) ? d_v : d_u;
    float*      out = (DIR == 0) ? d_u : d_v;

    __shared__ float red[RPB][TPB / 32];

    const int t = threadIdx.x;
    const int j0 = t * JPT;

    // Register-cache this thread's chunk of B points and weights, pre-scaled
    // into the log2 domain.
    float b0s[JPT], b1s[JPT], wk[JPT];
    const float4* B4 = (const float4*)B;   // 2 float2 points per float4
    const float4* W4 = (const float4*)w;
#pragma unroll
    for (int k = 0; k < JPT / 2; k++) {
        float4 p = B4[j0 / 2 + k];
        b0s[2 * k]     = p.x * SCL;  b1s[2 * k]     = p.y * SCL;
        b0s[2 * k + 1] = p.z * SCL;  b1s[2 * k + 1] = p.w * SCL;
    }
#pragma unroll
    for (int k = 0; k < JPT / 4; k++) {
        float4 ww = W4[j0 / 4 + k];
        wk[4 * k]     = ww.x * SCL;
        wk[4 * k + 1] = ww.y * SCL;
        wk[4 * k + 2] = ww.z * SCL;
        wk[4 * k + 3] = ww.w * SCL;
    }

    const int row0 = blockIdx.x * RPB;
    float axs[RPB], ays[RPB];
#pragma unroll
    for (int r = 0; r < RPB; r++) {
        float2 a = A[row0 + r];
        axs[r] = a.x * SCL;
        ays[r] = a.y * SCL;
    }

    // Single pass: unshifted sum of exp2 over all RPB rows.
    float s[RPB];
#pragma unroll
    for (int r = 0; r < RPB; r++) s[r] = 0.f;

#pragma unroll
    for (int r = 0; r < RPB; r++) {
#pragma unroll
        for (int k = 0; k < JPT; k++) {
            float dx = axs[r] - b0s[k];
            float dy = ays[r] - b1s[k];
            float c  = fabsf(dx) + fabsf(dy);   // abs folds into FADD operands
            s[r] += fast_ex2(wk[k] - c);        // exp2((w - C)/eps * log2e)
        }
    }

    // One batched reduction: 8 interleaved shuffle trees, one barrier.
#pragma unroll
    for (int o = 16; o; o >>= 1) {
#pragma unroll
        for (int r = 0; r < RPB; r++)
            s[r] += __shfl_xor_sync(0xffffffffu, s[r], o);
    }
    if ((t & 31) == 0) {
        const int wid = t >> 5;
#pragma unroll
        for (int r = 0; r < RPB; r++) red[r][wid] = s[r];
    }
    __syncthreads();

    if (t < RPB * (TPB / 32)) {           // 64 threads: 8 rows x 8 warp-partials
        const int r = t >> 3;
        float v = red[r][t & 7];
        v += __shfl_xor_sync(0xffffffffu, v, 4);
        v += __shfl_xor_sync(0xffffffffu, v, 2);
        v += __shfl_xor_sync(0xffffffffu, v, 1);
        if ((t & 7) == 0)
            out[row0 + r] = cmu - ELN2 * fast_lg2(v);   // cmu - EPS*ln(sum)
    }
}

// Writes pi and C, accumulates per-row sum(pi*C) into d_part[row].
__global__ __launch_bounds__(TPB) void final_kernel(const float2* __restrict__ X,
                                                    const float2* __restrict__ Y,
                                                    float* __restrict__ pi_out,
                                                    float* __restrict__ c_out) {
    __shared__ float red[TPB / 32];
    const int row = blockIdx.x;
    const int t = threadIdx.x;
    const float2 a = X[row];
    const float u10 = d_u[row] * IEPS;

    float s = 0.f;
    const int j0 = t * JPT;
#pragma unroll
    for (int k = 0; k < JPT; k++) {
        int j = j0 + k;
        float2 b = Y[j];
        float c  = fabsf(a.x - b.x) + fabsf(a.y - b.y);
        float arg = (u10 + d_v[j] * IEPS - c * IEPS) * K2E;
        float pi = fast_ex2(arg);
        size_t idx = (size_t)row * NPT + j;
        if (pi_out) pi_out[idx] = pi;
        if (c_out)  c_out[idx]  = c;
        s += pi * c;
    }
#pragma unroll
    for (int o = 16; o; o >>= 1) s += __shfl_xor_sync(0xffffffffu, s, o);
    if ((t & 31) == 0) red[t >> 5] = s;
    __syncthreads();
    if (t == 0) {
        float tot = 0.f;
#pragma unroll
        for (int i = 0; i < TPB / 32; i++) tot += red[i];
        d_part[row] = tot;
    }
}

// Deterministic final reduction of d_part into out[0] (double accumulation).
__global__ __launch_bounds__(TPB) void reduce_kernel(float* __restrict__ out) {
    __shared__ double red[TPB / 32];
    const int t = threadIdx.x;
    double s = 0.0;
    for (int i = t; i < NPT; i += TPB) s += (double)d_part[i];
#pragma unroll
    for (int o = 16; o; o >>= 1) s += __shfl_xor_sync(0xffffffffu, s, o);
    if ((t & 31) == 0) red[t >> 5] = s;
    __syncthreads();
    if (t == 0) {
        double tot = 0.0;
#pragma unroll
        for (int i = 0; i < TPB / 32; i++) tot += red[i];
        out[0] = (float)tot;
    }
}

extern "C" void kernel_launch(void* const* d_in, const int* in_sizes, int n_in,
                              void* d_out, int out_size) {
    const float2* x = (const float2*)d_in[0];
    const float2* y = (const float2*)d_in[1];
    float* out = (float*)d_out;

    // EPS * log(1/N + 1e-8)  (log_mu == log_nu since n == m)
    const float cmu = (float)(0.1 * log(1.0 / 4096.0 + 1e-8));

    init_uv<<<NPT / TPB, TPB>>>();

    for (int it = 0; it < 50; ++it) {
        lse_kernel<0><<<NPT / RPB, TPB>>>(x, y, cmu);  // update u (uses v)
        lse_kernel<1><<<NPT / RPB, TPB>>>(x, y, cmu);  // update v (uses new u)
    }

    // Output layout: [cost, pi (N*N row-major), C (N*N row-major)]
    float* pi_out = nullptr;
    float* c_out  = nullptr;
    const long long need = 1LL + 2LL * NPT * NPT;
    if ((long long)out_size >= need) {
        pi_out = out + 1;
        c_out  = out + 1 + (size_t)NPT * NPT;
    }
    final_kernel<<<NPT, TPB>>>(x, y, pi_out, c_out);
    reduce_kernel<<<1, TPB>>>(out);
}

// round 10
// speedup vs baseline: 2.0814x; 1.1094x over previous
#include <cuda_runtime.h>
#include <math.h>

#define NPT 4096
#define TPB 256
#define JPT 16          // j-elements per thread (NPT / TPB)
#define JPP (JPT / 2)   // packed pairs per thread
#define RPB 4           // rows per ticket group
#define NGROUPS (NPT / RPB)
#define GRID 444        // 148 SMs x 3 resident blocks -> single wave
#define EPSF 0.1f
#define IEPS 10.0f
#define K2E 1.4426950408889634f        // log2(e)
#define SCL (IEPS * K2E)               // 14.4269504...  (positive -> commutes with abs)
#define ELN2 0.0693147180559945f       // EPS * ln(2);  ELN2*SCL == 1 exactly

__device__ float d_u[NPT];
__device__ float d_v[NPT];
__device__ float d_wu[NPT];   // exp(u/eps) = 2^(u*SCL)
__device__ float d_wv[NPT];   // exp(v/eps)
__device__ float d_part[NPT];
__device__ int   d_tick[128]; // one ticket counter per lse launch

typedef unsigned long long ull;

__device__ __forceinline__ float fast_ex2(float x) {
    float r; asm("ex2.approx.ftz.f32 %0, %1;" : "=f"(r) : "f"(x)); return r;
}
__device__ __forceinline__ float fast_lg2(float x) {
    float r; asm("lg2.approx.ftz.f32 %0, %1;" : "=f"(r) : "f"(x)); return r;
}
__device__ __forceinline__ float fast_rcp(float x) {
    float r; asm("rcp.approx.ftz.f32 %0, %1;" : "=f"(r) : "f"(x)); return r;
}
__device__ __forceinline__ ull pk2(float lo, float hi) {
    ull r; asm("mov.b64 %0, {%1, %2};" : "=l"(r) : "f"(lo), "f"(hi)); return r;
}
__device__ __forceinline__ void unpk2(ull p, float& lo, float& hi) {
    asm("mov.b64 {%0, %1}, %2;" : "=f"(lo), "=f"(hi) : "l"(p));
}
__device__ __forceinline__ ull add2(ull a, ull b) {
    ull r; asm("add.rn.f32x2 %0, %1, %2;" : "=l"(r) : "l"(a), "l"(b)); return r;
}
__device__ __forceinline__ ull fma2(ull a, ull b, ull c) {
    ull r; asm("fma.rn.f32x2 %0, %1, %2, %3;" : "=l"(r) : "l"(a), "l"(b), "l"(c)); return r;
}

__global__ __launch_bounds__(TPB) void init_uv() {
    int i = blockIdx.x * TPB + threadIdx.x;
    if (i < NPT) {
        d_u[i] = 0.f;  d_v[i] = 0.f;
        d_wu[i] = 1.f; d_wv[i] = 1.f;   // exp(0/eps) = 1
    }
    if (i < 128) d_tick[i] = 0;
}

// Row update: S(row) = sum_j W[j] * 2^{-(|ax-bx|+|ay-by|) * SCL}
//   out[row]  = cmu - ELN2 * log2(S)
//   wout[row] = Kc / S          (== 2^{out*SCL}, since ELN2*SCL == 1)
// DIR==0: rows over X, reduce over Y with W = d_wv, out = d_u / d_wu
// DIR==1: rows over Y, reduce over X with W = d_wu, out = d_v / d_wv
template <int DIR>
__global__ __launch_bounds__(TPB, 3) void lse_kernel(const float2* __restrict__ X,
                                                     const float2* __restrict__ Y,
                                                     float cmu, float Kc, int tix) {
    const float2* A = (DIR == 0) ? X : Y;
    const float2* B = (DIR == 0) ? Y : X;
    const float2* W2 = (const float2*)((DIR == 0) ? d_wv : d_wu);
    float* out  = (DIR == 0) ? d_u  : d_v;
    float* wout = (DIR == 0) ? d_wu : d_wv;

    __shared__ float red[RPB][TPB / 32];
    __shared__ int sg;

    const int t = threadIdx.x;

    // ---- per-block prologue: register-cache this thread's B chunk + weights ----
    // thread t owns points j = t*JPT .. t*JPT+15, as JPP packed pairs.
    ull nbx[JPP], nby[JPP], Wp[JPP];
    {
        const float4* B4 = (const float4*)B;     // float4 = 2 float2 points
        const int m0 = t * JPP;                  // pair index base
#pragma unroll
        for (int k = 0; k < JPP; k++) {
            float4 p = B4[m0 + k];               // (bx0,by0,bx1,by1)
            nbx[k] = pk2(-p.x * SCL, -p.z * SCL);
            nby[k] = pk2(-p.y * SCL, -p.w * SCL);
            float2 ww = W2[m0 + k];
            Wp[k] = pk2(ww.x, ww.y);
        }
    }

    // first ticket
    if (t == 0) sg = atomicAdd(&d_tick[tix], 1);
    __syncthreads();
    int g = sg;

    while (g < NGROUPS) {
        if (t == 0) sg = atomicAdd(&d_tick[tix], 1);   // prefetch next

        const int row0 = g * RPB;
        ull sp[RPB];
#pragma unroll
        for (int r = 0; r < RPB; r++) sp[r] = 0;

#pragma unroll
        for (int r = 0; r < RPB; r++) {
            float2 a = A[row0 + r];               // broadcast load (L1 hit)
            const ull axp = pk2(a.x * SCL, a.x * SCL);
            const ull ayp = pk2(a.y * SCL, a.y * SCL);
#pragma unroll
            for (int k = 0; k < JPP; k++) {
                ull dx = add2(axp, nbx[k]);
                ull dy = add2(ayp, nby[k]);
                float dxl, dxh, dyl, dyh;
                unpk2(dx, dxl, dxh);
                unpk2(dy, dyl, dyh);
                float c0 = -fabsf(dxl) - fabsf(dyl);   // FADD with neg-abs mods
                float c1 = -fabsf(dxh) - fabsf(dyh);
                ull e = pk2(fast_ex2(c0), fast_ex2(c1));
                sp[r] = fma2(e, Wp[k], sp[r]);
            }
        }

        // batched reduction: unpack, RPB interleaved shuffle trees, one smem stage
        float s[RPB];
#pragma unroll
        for (int r = 0; r < RPB; r++) {
            float lo, hi; unpk2(sp[r], lo, hi);
            s[r] = lo + hi;
        }
#pragma unroll
        for (int o = 16; o; o >>= 1) {
#pragma unroll
            for (int r = 0; r < RPB; r++)
                s[r] += __shfl_xor_sync(0xffffffffu, s[r], o);
        }
        if ((t & 31) == 0) {
            const int wid = t >> 5;
#pragma unroll
            for (int r = 0; r < RPB; r++) red[r][wid] = s[r];
        }
        __syncthreads();

        if (t < RPB * (TPB / 32)) {       // 32 threads: RPB rows x 8 warp-partials
            const int r = t >> 3;
            float v = red[r][t & 7];
            v += __shfl_xor_sync(0xffffffffu, v, 4);
            v += __shfl_xor_sync(0xffffffffu, v, 2);
            v += __shfl_xor_sync(0xffffffffu, v, 1);
            if ((t & 7) == 0) {
                out[row0 + r]  = cmu - ELN2 * fast_lg2(v);
                wout[row0 + r] = Kc * fast_rcp(v);
            }
        }
        __syncthreads();     // red reuse + sg visible
        g = sg;
    }
}

// Writes pi and C, accumulates per-row sum(pi*C) into d_part.
// NOTE: pi_out / c_out are offset +1 float from the aligned harness buffer,
// so they are NOT 16B-aligned — scalar stores only. Loads (Y, d_v) stay
// vectorized; adjacent threads write adjacent 16B chunks so STG.32s coalesce.
__global__ __launch_bounds__(TPB) void final_kernel(const float2* __restrict__ X,
                                                    const float2* __restrict__ Y,
                                                    float* __restrict__ pi_out,
                                                    float* __restrict__ c_out) {
    __shared__ float red[TPB / 32];
    const int row = blockIdx.x;
    const int t = threadIdx.x;
    const float2 a = X[row];
    const float u10 = d_u[row] * IEPS;
    const float4* Y4 = (const float4*)Y;   // 2 points per float4
    const float4* V4 = (const float4*)d_v;

    float s = 0.f;
#pragma unroll
    for (int k = 0; k < NPT / (TPB * 4); k++) {
        const int jb = k * (TPB * 4) + t * 4;   // 4 consecutive j's
        float4 p0 = Y4[jb / 2];
        float4 p1 = Y4[jb / 2 + 1];
        float4 vv = V4[jb / 4];
        float c0 = fabsf(a.x - p0.x) + fabsf(a.y - p0.y);
        float c1 = fabsf(a.x - p0.z) + fabsf(a.y - p0.w);
        float c2 = fabsf(a.x - p1.x) + fabsf(a.y - p1.y);
        float c3 = fabsf(a.x - p1.z) + fabsf(a.y - p1.w);
        float pi0 = fast_ex2((u10 + vv.x * IEPS - c0 * IEPS) * K2E);
        float pi1 = fast_ex2((u10 + vv.y * IEPS - c1 * IEPS) * K2E);
        float pi2 = fast_ex2((u10 + vv.z * IEPS - c2 * IEPS) * K2E);
        float pi3 = fast_ex2((u10 + vv.w * IEPS - c3 * IEPS) * K2E);
        size_t idx = (size_t)row * NPT + jb;
        if (pi_out) {
            pi_out[idx]     = pi0;
            pi_out[idx + 1] = pi1;
            pi_out[idx + 2] = pi2;
            pi_out[idx + 3] = pi3;
        }
        if (c_out) {
            c_out[idx]     = c0;
            c_out[idx + 1] = c1;
            c_out[idx + 2] = c2;
            c_out[idx + 3] = c3;
        }
        s += pi0 * c0 + pi1 * c1 + pi2 * c2 + pi3 * c3;
    }
#pragma unroll
    for (int o = 16; o; o >>= 1) s += __shfl_xor_sync(0xffffffffu, s, o);
    if ((t & 31) == 0) red[t >> 5] = s;
    __syncthreads();
    if (t == 0) {
        float tot = 0.f;
#pragma unroll
        for (int i = 0; i < TPB / 32; i++) tot += red[i];
        d_part[row] = tot;
    }
}

// Deterministic final reduction of d_part into out[0] (double accumulation).
__global__ __launch_bounds__(TPB) void reduce_kernel(float* __restrict__ out) {
    __shared__ double red[TPB / 32];
    const int t = threadIdx.x;
    double s = 0.0;
    for (int i = t; i < NPT; i += TPB) s += (double)d_part[i];
#pragma unroll
    for (int o = 16; o; o >>= 1) s += __shfl_xor_sync(0xffffffffu, s, o);
    if ((t & 31) == 0) red[t >> 5] = s;
    __syncthreads();
    if (t == 0) {
        double tot = 0.0;
#pragma unroll
        for (int i = 0; i < TPB / 32; i++) tot += red[i];
        out[0] = (float)tot;
    }
}

extern "C" void kernel_launch(void* const* d_in, const int* in_sizes, int n_in,
                              void* d_out, int out_size) {
    const float2* x = (const float2*)d_in[0];
    const float2* y = (const float2*)d_in[1];
    float* out = (float*)d_out;

    // EPS * log(1/N + 1e-8)  (log_mu == log_nu since n == m)
    const double cmu_d = 0.1 * log(1.0 / 4096.0 + 1e-8);
    const float cmu = (float)cmu_d;
    const float Kc  = (float)exp2(cmu_d * (10.0 * 1.4426950408889634));  // 2^(cmu*SCL)

    init_uv<<<NPT / TPB, TPB>>>();

    for (int it = 0; it < 50; ++it) {
        lse_kernel<0><<<GRID, TPB>>>(x, y, cmu, Kc, 2 * it);     // update u (uses v)
        lse_kernel<1><<<GRID, TPB>>>(x, y, cmu, Kc, 2 * it + 1); // update v (uses new u)
    }

    // Output layout: [cost, pi (N*N row-major), C (N*N row-major)]
    float* pi_out = nullptr;
    float* c_out  = nullptr;
    const long long need = 1LL + 2LL * NPT * NPT;
    if ((long long)out_size >= need) {
        pi_out = out + 1;
        c_out  = out + 1 + (size_t)NPT * NPT;
    }
    final_kernel<<<NPT, TPB>>>(x, y, pi_out, c_out);
    reduce_kernel<<<1, TPB>>>(out);
}